// round 7
// baseline (speedup 1.0000x reference)
#include <cuda_runtime.h>
#include <cuda_fp16.h>

#define NN 100000
#define NN_PAD 102400
#define EE 1600000
#define FIN 100
#define XS_W 104          // fp16 row width (13 x 8 halves, 16B chunks)
#define HID 128
#define NC 47
#define NC_PAD 48

// GEMM tiling
#define CK 16
#define RS_A 73
#define RS_B1 136
#define RS_B2 56

__device__ int    g_degi[NN_PAD];
__device__ int    g_rowstart[NN];
__device__ int    g_eord[EE];
__device__ int    g_csr[EE];
__device__ float  g_dinv[NN];
__device__ __half g_xs[NN * XS_W];     // fp16( dinv[s] * x[s] ), padded rows
__device__ float  g_aggx[NN * FIN];
__device__ float  g_h[NN * HID];
__device__ __half g_hws[NN * NC_PAD];  // fp16( dinv[r] * (h@W2)[r] )

__device__ __forceinline__ void mma_tf32(float c[4], unsigned a0, unsigned a1,
                                         unsigned a2, unsigned a3,
                                         unsigned b0, unsigned b1) {
    asm volatile(
        "mma.sync.aligned.m16n8k8.row.col.f32.tf32.tf32.f32 "
        "{%0,%1,%2,%3}, {%4,%5,%6,%7}, {%8,%9}, {%0,%1,%2,%3};"
        : "+f"(c[0]), "+f"(c[1]), "+f"(c[2]), "+f"(c[3])
        : "r"(a0), "r"(a1), "r"(a2), "r"(a3), "r"(b0), "r"(b1));
}

__device__ __forceinline__ void split_hl(float v, float& hi, float& lo) {
    unsigned hbits = __float_as_uint(v) & 0xffffe000u;
    hi = __uint_as_float(hbits);
    lo = v - hi;
}

__device__ __forceinline__ void acc8_add(float acc[8], uint4 v) {
    __half2* h = (__half2*)&v;
    float2 f0 = __half22float2(h[0]);
    float2 f1 = __half22float2(h[1]);
    float2 f2 = __half22float2(h[2]);
    float2 f3 = __half22float2(h[3]);
    acc[0] += f0.x; acc[1] += f0.y;
    acc[2] += f1.x; acc[3] += f1.y;
    acc[4] += f2.x; acc[5] += f2.y;
    acc[6] += f3.x; acc[7] += f3.y;
}

// ---------------- CSR build ----------------
__global__ void k_deg(const int* __restrict__ ei) {
    int e = blockIdx.x * blockDim.x + threadIdx.x;
    if (e < EE) g_eord[e] = atomicAdd(&g_degi[ei[EE + e]], 1);
}

__global__ void k_scan() {
    __shared__ int sh_w[32];
    __shared__ int sh_tot;
    int tid = threadIdx.x;
    int lane = tid & 31, wid = tid >> 5;
    int carry = 0;
    for (int base = 0; base < NN_PAD; base += 4096) {
        int i0 = base + tid * 4;
        int4 d = ((const int4*)g_degi)[i0 >> 2];
        int s0 = d.x, s1 = s0 + d.y, s2 = s1 + d.z, s3 = s2 + d.w;
        int tsum = s3;
        int v = tsum;
        #pragma unroll
        for (int off = 1; off < 32; off <<= 1) {
            int t = __shfl_up_sync(0xffffffffu, v, off);
            if (lane >= off) v += t;
        }
        int wexcl = v - tsum;
        if (lane == 31) sh_w[wid] = v;
        __syncthreads();
        if (wid == 0) {
            int wv = sh_w[lane];
            int u = wv;
            #pragma unroll
            for (int off = 1; off < 32; off <<= 1) {
                int t = __shfl_up_sync(0xffffffffu, u, off);
                if (lane >= off) u += t;
            }
            sh_w[lane] = u - wv;
            if (lane == 31) sh_tot = u;
        }
        __syncthreads();
        int off0 = carry + sh_w[wid] + wexcl;
        if (i0 + 0 < NN) { g_rowstart[i0 + 0] = off0;      g_dinv[i0 + 0] = rsqrtf((float)d.x + 1.f); }
        if (i0 + 1 < NN) { g_rowstart[i0 + 1] = off0 + s0; g_dinv[i0 + 1] = rsqrtf((float)d.y + 1.f); }
        if (i0 + 2 < NN) { g_rowstart[i0 + 2] = off0 + s1; g_dinv[i0 + 2] = rsqrtf((float)d.z + 1.f); }
        if (i0 + 3 < NN) { g_rowstart[i0 + 3] = off0 + s2; g_dinv[i0 + 3] = rsqrtf((float)d.w + 1.f); }
        carry += sh_tot;
        __syncthreads();
    }
}

// fill CSR + build fp16 scaled feature table (needs dinv => after scan)
__global__ void k_fill_conv(const int* __restrict__ ei, const float* __restrict__ x) {
    int t = blockIdx.x * blockDim.x + threadIdx.x;
    if (t < EE)
        g_csr[g_rowstart[ei[EE + t]] + g_eord[t]] = ei[t];
    if (t < NN * 13) {
        int n = t / 13, c = t - n * 13;
        float w = g_dinv[n];
        int base = c * 8;
        float f[8];
#pragma unroll
        for (int i = 0; i < 8; i++) {
            int col = base + i;
            float v = 0.f;
            if (col < FIN) v = x[n * FIN + col] * w;
            f[i] = v;
        }
        __half2 hh[4];
        hh[0] = __floats2half2_rn(f[0], f[1]);
        hh[1] = __floats2half2_rn(f[2], f[3]);
        hh[2] = __floats2half2_rn(f[4], f[5]);
        hh[3] = __floats2half2_rn(f[6], f[7]);
        ((uint4*)g_xs)[n * 13 + c] = *(uint4*)hh;
    }
}

// ---------------- layer 1 aggregation: warp per node, fp16 gathers ----------------
// aggx[d] = dinv[d] * ( xs[d] + sum_s xs[s] ),  xs already dinv-scaled
__global__ void k_agg1() {
    int t = blockIdx.x * blockDim.x + threadIdx.x;
    int node = t >> 5, lane = t & 31;
    if (node >= NN) return;
    bool act = lane < 13;
    const uint4* xs4 = (const uint4*)g_xs;   // 13 uint4 per row
    float acc[8] = {0.f, 0.f, 0.f, 0.f, 0.f, 0.f, 0.f, 0.f};
    if (act) acc8_add(acc, xs4[node * 13 + lane]);   // self loop term
    int start = g_rowstart[node];
    int end = start + g_degi[node];
    int j = start;
    for (; j + 1 < end; j += 2) {
        int s0 = g_csr[j], s1 = g_csr[j + 1];
        if (act) {
            acc8_add(acc, xs4[s0 * 13 + lane]);
            acc8_add(acc, xs4[s1 * 13 + lane]);
        }
    }
    if (j < end) {
        int s0 = g_csr[j];
        if (act) acc8_add(acc, xs4[s0 * 13 + lane]);
    }
    if (act) {
        float wd = g_dinv[node];
#pragma unroll
        for (int i = 0; i < 8; i++) acc[i] *= wd;
        int ob = node * FIN + lane * 8;
        *(float4*)&g_aggx[ob] = make_float4(acc[0], acc[1], acc[2], acc[3]);
        if (lane < 12)
            *(float4*)&g_aggx[ob + 4] = make_float4(acc[4], acc[5], acc[6], acc[7]);
    }
}

// ---------------- GEMM1 (3xTF32 mma): g_h = relu(g_aggx @ W1 + b1) ----------------
__global__ void __launch_bounds__(128) k_gemm1(const float* __restrict__ W1,
                                               const float* __restrict__ b1) {
    __shared__ float As_hi[CK * RS_A], As_lo[CK * RS_A];
    __shared__ float Bs_hi[CK * RS_B1], Bs_lo[CK * RS_B1];
    int tid = threadIdx.x;
    int lane = tid & 31, wid = tid >> 5;
    int g = lane >> 2, q = lane & 3;
    int warp_m = wid & 1, warp_n = wid >> 1;
    int row0 = blockIdx.x * 64;
    float c[2][8][4];
#pragma unroll
    for (int mt = 0; mt < 2; mt++)
#pragma unroll
        for (int nt = 0; nt < 8; nt++)
#pragma unroll
            for (int r = 0; r < 4; r++) c[mt][nt][r] = 0.f;

    for (int kc = 0; kc < FIN; kc += CK) {
        int kw = FIN - kc; if (kw > CK) kw = CK;
        __syncthreads();
        for (int i = tid; i < 64 * CK; i += 128) {
            int m = i >> 4, k = i & 15;
            float v = 0.f;
            int gr = row0 + m;
            if (k < kw && gr < NN) v = g_aggx[gr * FIN + kc + k];
            float hi, lo; split_hl(v, hi, lo);
            As_hi[k * RS_A + m] = hi;
            As_lo[k * RS_A + m] = lo;
        }
        for (int i = tid; i < CK * HID; i += 128) {
            int k = i >> 7, n = i & 127;
            float v = (k < kw) ? W1[(kc + k) * HID + n] : 0.f;
            float hi, lo; split_hl(v, hi, lo);
            Bs_hi[k * RS_B1 + n] = hi;
            Bs_lo[k * RS_B1 + n] = lo;
        }
        __syncthreads();
#pragma unroll
        for (int kk = 0; kk < CK; kk += 8) {
            unsigned ah[2][4], al[2][4];
#pragma unroll
            for (int mt = 0; mt < 2; mt++) {
                int mi = warp_m * 32 + mt * 16 + g;
                int r0 = (kk + q) * RS_A, r1 = (kk + q + 4) * RS_A;
                ah[mt][0] = __float_as_uint(As_hi[r0 + mi]);
                ah[mt][1] = __float_as_uint(As_hi[r0 + mi + 8]);
                ah[mt][2] = __float_as_uint(As_hi[r1 + mi]);
                ah[mt][3] = __float_as_uint(As_hi[r1 + mi + 8]);
                al[mt][0] = __float_as_uint(As_lo[r0 + mi]);
                al[mt][1] = __float_as_uint(As_lo[r0 + mi + 8]);
                al[mt][2] = __float_as_uint(As_lo[r1 + mi]);
                al[mt][3] = __float_as_uint(As_lo[r1 + mi + 8]);
            }
#pragma unroll
            for (int nt = 0; nt < 8; nt++) {
                int ni = warp_n * 64 + nt * 8 + g;
                int r0 = (kk + q) * RS_B1, r1 = (kk + q + 4) * RS_B1;
                unsigned bh0 = __float_as_uint(Bs_hi[r0 + ni]);
                unsigned bh1 = __float_as_uint(Bs_hi[r1 + ni]);
                unsigned bl0 = __float_as_uint(Bs_lo[r0 + ni]);
                unsigned bl1 = __float_as_uint(Bs_lo[r1 + ni]);
#pragma unroll
                for (int mt = 0; mt < 2; mt++) {
                    mma_tf32(c[mt][nt], ah[mt][0], ah[mt][1], ah[mt][2], ah[mt][3], bh0, bh1);
                    mma_tf32(c[mt][nt], al[mt][0], al[mt][1], al[mt][2], al[mt][3], bh0, bh1);
                    mma_tf32(c[mt][nt], ah[mt][0], ah[mt][1], ah[mt][2], ah[mt][3], bl0, bl1);
                }
            }
        }
    }
#pragma unroll
    for (int mt = 0; mt < 2; mt++) {
        int row = row0 + warp_m * 32 + mt * 16 + g;
#pragma unroll
        for (int nt = 0; nt < 8; nt++) {
            int col = warp_n * 64 + nt * 8 + 2 * q;
            float bb0 = b1[col], bb1 = b1[col + 1];
            if (row < NN) {
                float v0 = c[mt][nt][0] + bb0, v1 = c[mt][nt][1] + bb1;
                float2 o = make_float2(v0 > 0.f ? v0 : 0.f, v1 > 0.f ? v1 : 0.f);
                *(float2*)&g_h[row * HID + col] = o;
            }
            if (row + 8 < NN) {
                float v2 = c[mt][nt][2] + bb0, v3 = c[mt][nt][3] + bb1;
                float2 o = make_float2(v2 > 0.f ? v2 : 0.f, v3 > 0.f ? v3 : 0.f);
                *(float2*)&g_h[(row + 8) * HID + col] = o;
            }
        }
    }
}

// ---------------- GEMM2 (3xTF32 mma): g_hws = fp16( dinv * (g_h @ W2) ) ----------------
__global__ void __launch_bounds__(128) k_gemm2(const float* __restrict__ W2) {
    __shared__ float As_hi[CK * RS_A], As_lo[CK * RS_A];
    __shared__ float Bs_hi[CK * RS_B2], Bs_lo[CK * RS_B2];
    int tid = threadIdx.x;
    int lane = tid & 31, wid = tid >> 5;
    int g = lane >> 2, q = lane & 3;
    int row0 = blockIdx.x * 64;
    float c[6][4];
#pragma unroll
    for (int nt = 0; nt < 6; nt++)
#pragma unroll
        for (int r = 0; r < 4; r++) c[nt][r] = 0.f;

    for (int kc = 0; kc < HID; kc += CK) {
        __syncthreads();
        for (int i = tid; i < 64 * CK; i += 128) {
            int m = i >> 4, k = i & 15;
            int gr = row0 + m;
            float v = (gr < NN) ? g_h[gr * HID + kc + k] : 0.f;
            float hi, lo; split_hl(v, hi, lo);
            As_hi[k * RS_A + m] = hi;
            As_lo[k * RS_A + m] = lo;
        }
        for (int i = tid; i < CK * NC_PAD; i += 128) {
            int k = i / NC_PAD, n = i - k * NC_PAD;
            float v = (n < NC) ? W2[(kc + k) * NC + n] : 0.f;
            float hi, lo; split_hl(v, hi, lo);
            Bs_hi[k * RS_B2 + n] = hi;
            Bs_lo[k * RS_B2 + n] = lo;
        }
        __syncthreads();
#pragma unroll
        for (int kk = 0; kk < CK; kk += 8) {
            int mi = wid * 16 + g;
            int ra0 = (kk + q) * RS_A, ra1 = (kk + q + 4) * RS_A;
            unsigned a0 = __float_as_uint(As_hi[ra0 + mi]);
            unsigned a1 = __float_as_uint(As_hi[ra0 + mi + 8]);
            unsigned a2 = __float_as_uint(As_hi[ra1 + mi]);
            unsigned a3 = __float_as_uint(As_hi[ra1 + mi + 8]);
            unsigned l0 = __float_as_uint(As_lo[ra0 + mi]);
            unsigned l1 = __float_as_uint(As_lo[ra0 + mi + 8]);
            unsigned l2 = __float_as_uint(As_lo[ra1 + mi]);
            unsigned l3 = __float_as_uint(As_lo[ra1 + mi + 8]);
#pragma unroll
            for (int nt = 0; nt < 6; nt++) {
                int ni = nt * 8 + g;
                int rb0 = (kk + q) * RS_B2, rb1 = (kk + q + 4) * RS_B2;
                unsigned bh0 = __float_as_uint(Bs_hi[rb0 + ni]);
                unsigned bh1 = __float_as_uint(Bs_hi[rb1 + ni]);
                unsigned bl0 = __float_as_uint(Bs_lo[rb0 + ni]);
                unsigned bl1 = __float_as_uint(Bs_lo[rb1 + ni]);
                mma_tf32(c[nt], a0, a1, a2, a3, bh0, bh1);
                mma_tf32(c[nt], l0, l1, l2, l3, bh0, bh1);
                mma_tf32(c[nt], a0, a1, a2, a3, bl0, bl1);
            }
        }
    }
    int row = row0 + wid * 16 + g;
    float wd0 = (row < NN) ? g_dinv[row] : 0.f;
    float wd1 = (row + 8 < NN) ? g_dinv[row + 8] : 0.f;
#pragma unroll
    for (int nt = 0; nt < 6; nt++) {
        int col = nt * 8 + 2 * q;
        if (row < NN)
            *(__half2*)&g_hws[row * NC_PAD + col] =
                __floats2half2_rn(c[nt][0] * wd0, c[nt][1] * wd0);
        if (row + 8 < NN)
            *(__half2*)&g_hws[(row + 8) * NC_PAD + col] =
                __floats2half2_rn(c[nt][2] * wd1, c[nt][3] * wd1);
    }
}

// ---------------- layer 2 aggregation: 8 threads per node, fp16 gathers ----------------
// out[d] = dinv[d] * ( hws[d] + sum_s hws[s] ) + b2
__global__ void k_agg2(const float* __restrict__ b2, float* __restrict__ out) {
    int t = blockIdx.x * blockDim.x + threadIdx.x;
    int node = t >> 3, sub = t & 7;
    if (node >= NN) return;
    bool act = sub < 6;
    const uint4* hw4 = (const uint4*)g_hws;   // 6 uint4 per row
    float acc[8] = {0.f, 0.f, 0.f, 0.f, 0.f, 0.f, 0.f, 0.f};
    if (act) acc8_add(acc, hw4[node * 6 + sub]);   // self loop term
    int start = g_rowstart[node];
    int end = start + g_degi[node];
    int j = start;
    for (; j + 1 < end; j += 2) {
        int s0 = g_csr[j], s1 = g_csr[j + 1];
        if (act) {
            acc8_add(acc, hw4[s0 * 6 + sub]);
            acc8_add(acc, hw4[s1 * 6 + sub]);
        }
    }
    if (j < end) {
        int s0 = g_csr[j];
        if (act) acc8_add(acc, hw4[s0 * 6 + sub]);
    }
    if (act) {
        float wd = g_dinv[node];
        int cb = sub * 8;
#pragma unroll
        for (int i = 0; i < 8; i++) {
            int col = cb + i;
            if (col < NC) out[node * NC + col] = acc[i] * wd + b2[col];
        }
    }
}

extern "C" void kernel_launch(void* const* d_in, const int* in_sizes, int n_in,
                              void* d_out, int out_size) {
    const float* x  = (const float*)d_in[0];
    const int*   ei = (const int*)d_in[1];
    const float* W1 = (const float*)d_in[2];
    const float* b1 = (const float*)d_in[3];
    const float* W2 = (const float*)d_in[4];
    const float* b2 = (const float*)d_in[5];
    float* out = (float*)d_out;

    void* degi_ptr = nullptr;
    cudaGetSymbolAddress(&degi_ptr, g_degi);
    cudaMemsetAsync(degi_ptr, 0, NN_PAD * sizeof(int));

    k_deg<<<(EE + 255) / 256, 256>>>(ei);               // 0
    k_scan<<<1, 1024>>>();                              // 1
    k_fill_conv<<<(EE + 255) / 256, 256>>>(ei, x);      // 2 (fill + fp16 table)
    k_agg1<<<(NN * 32 + 255) / 256, 256>>>();           // 3 (profiled)
    k_gemm1<<<(NN + 63) / 64, 128>>>(W1, b1);           // 4
    k_gemm2<<<(NN + 63) / 64, 128>>>(W2);               // 5
    k_agg2<<<(NN * 8 + 255) / 256, 256>>>(b2, out);     // 6
}

// round 8
// speedup vs baseline: 1.0406x; 1.0406x over previous
#include <cuda_runtime.h>
#include <cuda_fp16.h>

#define NN 100000
#define NN_PAD 102400
#define EE 1600000
#define FIN 100
#define XS_W 104          // fp16 row width (13 x 8 halves, 16B chunks)
#define HID 128
#define NC 47
#define NC_PAD 48

// GEMM tiling
#define CK 16
#define RS_A 73
#define RS_B1 136
#define RS_B2 56

__device__ int    g_degi[NN_PAD];
__device__ int    g_rowstart[NN];
__device__ int    g_eord[EE];
__device__ int    g_csr[EE];
__device__ float  g_dinv[NN];
__device__ __half g_xs[NN * XS_W];     // fp16( dinv[s] * x[s] ), padded rows
__device__ float  g_aggx[NN * FIN];
__device__ float  g_h[NN * HID];
__device__ __half g_hws[NN * NC_PAD];  // fp16( dinv[r] * (h@W2)[r] )

__device__ __forceinline__ void mma_tf32(float c[4], unsigned a0, unsigned a1,
                                         unsigned a2, unsigned a3,
                                         unsigned b0, unsigned b1) {
    asm volatile(
        "mma.sync.aligned.m16n8k8.row.col.f32.tf32.tf32.f32 "
        "{%0,%1,%2,%3}, {%4,%5,%6,%7}, {%8,%9}, {%0,%1,%2,%3};"
        : "+f"(c[0]), "+f"(c[1]), "+f"(c[2]), "+f"(c[3])
        : "r"(a0), "r"(a1), "r"(a2), "r"(a3), "r"(b0), "r"(b1));
}

__device__ __forceinline__ void split_hl(float v, float& hi, float& lo) {
    unsigned hbits = __float_as_uint(v) & 0xffffe000u;
    hi = __uint_as_float(hbits);
    lo = v - hi;
}

// exact fp32 convert-add of one uint4 of halves
__device__ __forceinline__ void acc8_add(float acc[8], uint4 v) {
    __half2* h = (__half2*)&v;
    float2 f0 = __half22float2(h[0]);
    float2 f1 = __half22float2(h[1]);
    float2 f2 = __half22float2(h[2]);
    float2 f3 = __half22float2(h[3]);
    acc[0] += f0.x; acc[1] += f0.y;
    acc[2] += f1.x; acc[3] += f1.y;
    acc[4] += f2.x; acc[5] += f2.y;
    acc[6] += f3.x; acc[7] += f3.y;
}

// fp16 tree-reduce 4 rows, one convert, fp32 accumulate (3 HADD2 + 2 F2F + 2 FADD per slot)
__device__ __forceinline__ void acc8_add4(float acc[8], uint4 a, uint4 b, uint4 c, uint4 d) {
    __half2* ha = (__half2*)&a;
    __half2* hb = (__half2*)&b;
    __half2* hc = (__half2*)&c;
    __half2* hd = (__half2*)&d;
#pragma unroll
    for (int k = 0; k < 4; k++) {
        __half2 s = __hadd2(__hadd2(ha[k], hb[k]), __hadd2(hc[k], hd[k]));
        float2 f = __half22float2(s);
        acc[2 * k] += f.x;
        acc[2 * k + 1] += f.y;
    }
}

// ---------------- CSR build ----------------
__global__ void k_deg(const int* __restrict__ ei) {
    int e = blockIdx.x * blockDim.x + threadIdx.x;
    if (e < EE) g_eord[e] = atomicAdd(&g_degi[ei[EE + e]], 1);
}

__global__ void k_scan() {
    __shared__ int sh_w[32];
    __shared__ int sh_tot;
    int tid = threadIdx.x;
    int lane = tid & 31, wid = tid >> 5;
    int carry = 0;
    for (int base = 0; base < NN_PAD; base += 4096) {
        int i0 = base + tid * 4;
        int4 d = ((const int4*)g_degi)[i0 >> 2];
        int s0 = d.x, s1 = s0 + d.y, s2 = s1 + d.z, s3 = s2 + d.w;
        int tsum = s3;
        int v = tsum;
        #pragma unroll
        for (int off = 1; off < 32; off <<= 1) {
            int t = __shfl_up_sync(0xffffffffu, v, off);
            if (lane >= off) v += t;
        }
        int wexcl = v - tsum;
        if (lane == 31) sh_w[wid] = v;
        __syncthreads();
        if (wid == 0) {
            int wv = sh_w[lane];
            int u = wv;
            #pragma unroll
            for (int off = 1; off < 32; off <<= 1) {
                int t = __shfl_up_sync(0xffffffffu, u, off);
                if (lane >= off) u += t;
            }
            sh_w[lane] = u - wv;
            if (lane == 31) sh_tot = u;
        }
        __syncthreads();
        int off0 = carry + sh_w[wid] + wexcl;
        if (i0 + 0 < NN) { g_rowstart[i0 + 0] = off0;      g_dinv[i0 + 0] = rsqrtf((float)d.x + 1.f); }
        if (i0 + 1 < NN) { g_rowstart[i0 + 1] = off0 + s0; g_dinv[i0 + 1] = rsqrtf((float)d.y + 1.f); }
        if (i0 + 2 < NN) { g_rowstart[i0 + 2] = off0 + s1; g_dinv[i0 + 2] = rsqrtf((float)d.z + 1.f); }
        if (i0 + 3 < NN) { g_rowstart[i0 + 3] = off0 + s2; g_dinv[i0 + 3] = rsqrtf((float)d.w + 1.f); }
        carry += sh_tot;
        __syncthreads();
    }
}

// fill CSR + build fp16 scaled feature table (needs dinv => after scan)
__global__ void k_fill_conv(const int* __restrict__ ei, const float* __restrict__ x) {
    int t = blockIdx.x * blockDim.x + threadIdx.x;
    if (t < EE)
        g_csr[g_rowstart[ei[EE + t]] + g_eord[t]] = ei[t];
    if (t < NN * 13) {
        int n = t / 13, c = t - n * 13;
        float w = g_dinv[n];
        int base = c * 8;
        float f[8];
#pragma unroll
        for (int i = 0; i < 8; i++) {
            int col = base + i;
            float v = 0.f;
            if (col < FIN) v = x[n * FIN + col] * w;
            f[i] = v;
        }
        __half2 hh[4];
        hh[0] = __floats2half2_rn(f[0], f[1]);
        hh[1] = __floats2half2_rn(f[2], f[3]);
        hh[2] = __floats2half2_rn(f[4], f[5]);
        hh[3] = __floats2half2_rn(f[6], f[7]);
        ((uint4*)g_xs)[n * 13 + c] = *(uint4*)hh;
    }
}

// ---------------- layer 1 aggregation: warp per node, fp16 tree gathers ----------------
// aggx[d] = dinv[d] * ( xs[d] + sum_s xs[s] ),  xs already dinv-scaled
__global__ void k_agg1() {
    int t = blockIdx.x * blockDim.x + threadIdx.x;
    int node = t >> 5, lane = t & 31;
    if (node >= NN) return;
    bool act = lane < 13;
    const uint4* xs4 = (const uint4*)g_xs;   // 13 uint4 per row
    float acc[8] = {0.f, 0.f, 0.f, 0.f, 0.f, 0.f, 0.f, 0.f};
    if (act) acc8_add(acc, xs4[node * 13 + lane]);   // self loop (exact)
    int start = g_rowstart[node];
    int end = start + g_degi[node];
    int j = start;
    for (; j + 3 < end; j += 4) {
        int s0 = g_csr[j], s1 = g_csr[j + 1], s2 = g_csr[j + 2], s3 = g_csr[j + 3];
        if (act) {
            uint4 v0 = xs4[s0 * 13 + lane];
            uint4 v1 = xs4[s1 * 13 + lane];
            uint4 v2 = xs4[s2 * 13 + lane];
            uint4 v3 = xs4[s3 * 13 + lane];
            acc8_add4(acc, v0, v1, v2, v3);
        }
    }
    for (; j < end; j++) {
        int s0 = g_csr[j];
        if (act) acc8_add(acc, xs4[s0 * 13 + lane]);   // exact remainder
    }
    if (act) {
        float wd = g_dinv[node];
#pragma unroll
        for (int i = 0; i < 8; i++) acc[i] *= wd;
        int ob = node * FIN + lane * 8;
        *(float4*)&g_aggx[ob] = make_float4(acc[0], acc[1], acc[2], acc[3]);
        if (lane < 12)
            *(float4*)&g_aggx[ob + 4] = make_float4(acc[4], acc[5], acc[6], acc[7]);
    }
}

// ---------------- GEMM1 (3xTF32 mma): g_h = relu(g_aggx @ W1 + b1) ----------------
__global__ void __launch_bounds__(128) k_gemm1(const float* __restrict__ W1,
                                               const float* __restrict__ b1) {
    __shared__ float As_hi[CK * RS_A], As_lo[CK * RS_A];
    __shared__ float Bs_hi[CK * RS_B1], Bs_lo[CK * RS_B1];
    int tid = threadIdx.x;
    int lane = tid & 31, wid = tid >> 5;
    int g = lane >> 2, q = lane & 3;
    int warp_m = wid & 1, warp_n = wid >> 1;
    int row0 = blockIdx.x * 64;
    float c[2][8][4];
#pragma unroll
    for (int mt = 0; mt < 2; mt++)
#pragma unroll
        for (int nt = 0; nt < 8; nt++)
#pragma unroll
            for (int r = 0; r < 4; r++) c[mt][nt][r] = 0.f;

    for (int kc = 0; kc < FIN; kc += CK) {
        int kw = FIN - kc; if (kw > CK) kw = CK;
        __syncthreads();
        for (int i = tid; i < 64 * CK; i += 128) {
            int m = i >> 4, k = i & 15;
            float v = 0.f;
            int gr = row0 + m;
            if (k < kw && gr < NN) v = g_aggx[gr * FIN + kc + k];
            float hi, lo; split_hl(v, hi, lo);
            As_hi[k * RS_A + m] = hi;
            As_lo[k * RS_A + m] = lo;
        }
        for (int i = tid; i < CK * HID; i += 128) {
            int k = i >> 7, n = i & 127;
            float v = (k < kw) ? W1[(kc + k) * HID + n] : 0.f;
            float hi, lo; split_hl(v, hi, lo);
            Bs_hi[k * RS_B1 + n] = hi;
            Bs_lo[k * RS_B1 + n] = lo;
        }
        __syncthreads();
#pragma unroll
        for (int kk = 0; kk < CK; kk += 8) {
            unsigned ah[2][4], al[2][4];
#pragma unroll
            for (int mt = 0; mt < 2; mt++) {
                int mi = warp_m * 32 + mt * 16 + g;
                int r0 = (kk + q) * RS_A, r1 = (kk + q + 4) * RS_A;
                ah[mt][0] = __float_as_uint(As_hi[r0 + mi]);
                ah[mt][1] = __float_as_uint(As_hi[r0 + mi + 8]);
                ah[mt][2] = __float_as_uint(As_hi[r1 + mi]);
                ah[mt][3] = __float_as_uint(As_hi[r1 + mi + 8]);
                al[mt][0] = __float_as_uint(As_lo[r0 + mi]);
                al[mt][1] = __float_as_uint(As_lo[r0 + mi + 8]);
                al[mt][2] = __float_as_uint(As_lo[r1 + mi]);
                al[mt][3] = __float_as_uint(As_lo[r1 + mi + 8]);
            }
#pragma unroll
            for (int nt = 0; nt < 8; nt++) {
                int ni = warp_n * 64 + nt * 8 + g;
                int r0 = (kk + q) * RS_B1, r1 = (kk + q + 4) * RS_B1;
                unsigned bh0 = __float_as_uint(Bs_hi[r0 + ni]);
                unsigned bh1 = __float_as_uint(Bs_hi[r1 + ni]);
                unsigned bl0 = __float_as_uint(Bs_lo[r0 + ni]);
                unsigned bl1 = __float_as_uint(Bs_lo[r1 + ni]);
#pragma unroll
                for (int mt = 0; mt < 2; mt++) {
                    mma_tf32(c[mt][nt], ah[mt][0], ah[mt][1], ah[mt][2], ah[mt][3], bh0, bh1);
                    mma_tf32(c[mt][nt], al[mt][0], al[mt][1], al[mt][2], al[mt][3], bh0, bh1);
                    mma_tf32(c[mt][nt], ah[mt][0], ah[mt][1], ah[mt][2], ah[mt][3], bl0, bl1);
                }
            }
        }
    }
#pragma unroll
    for (int mt = 0; mt < 2; mt++) {
        int row = row0 + warp_m * 32 + mt * 16 + g;
#pragma unroll
        for (int nt = 0; nt < 8; nt++) {
            int col = warp_n * 64 + nt * 8 + 2 * q;
            float bb0 = b1[col], bb1 = b1[col + 1];
            if (row < NN) {
                float v0 = c[mt][nt][0] + bb0, v1 = c[mt][nt][1] + bb1;
                float2 o = make_float2(v0 > 0.f ? v0 : 0.f, v1 > 0.f ? v1 : 0.f);
                *(float2*)&g_h[row * HID + col] = o;
            }
            if (row + 8 < NN) {
                float v2 = c[mt][nt][2] + bb0, v3 = c[mt][nt][3] + bb1;
                float2 o = make_float2(v2 > 0.f ? v2 : 0.f, v3 > 0.f ? v3 : 0.f);
                *(float2*)&g_h[(row + 8) * HID + col] = o;
            }
        }
    }
}

// ---------------- GEMM2 (3xTF32 mma): g_hws = fp16( dinv * (g_h @ W2) ) ----------------
__global__ void __launch_bounds__(128) k_gemm2(const float* __restrict__ W2) {
    __shared__ float As_hi[CK * RS_A], As_lo[CK * RS_A];
    __shared__ float Bs_hi[CK * RS_B2], Bs_lo[CK * RS_B2];
    int tid = threadIdx.x;
    int lane = tid & 31, wid = tid >> 5;
    int g = lane >> 2, q = lane & 3;
    int row0 = blockIdx.x * 64;
    float c[6][4];
#pragma unroll
    for (int nt = 0; nt < 6; nt++)
#pragma unroll
        for (int r = 0; r < 4; r++) c[nt][r] = 0.f;

    for (int kc = 0; kc < HID; kc += CK) {
        __syncthreads();
        for (int i = tid; i < 64 * CK; i += 128) {
            int m = i >> 4, k = i & 15;
            int gr = row0 + m;
            float v = (gr < NN) ? g_h[gr * HID + kc + k] : 0.f;
            float hi, lo; split_hl(v, hi, lo);
            As_hi[k * RS_A + m] = hi;
            As_lo[k * RS_A + m] = lo;
        }
        for (int i = tid; i < CK * NC_PAD; i += 128) {
            int k = i / NC_PAD, n = i - k * NC_PAD;
            float v = (n < NC) ? W2[(kc + k) * NC + n] : 0.f;
            float hi, lo; split_hl(v, hi, lo);
            Bs_hi[k * RS_B2 + n] = hi;
            Bs_lo[k * RS_B2 + n] = lo;
        }
        __syncthreads();
#pragma unroll
        for (int kk = 0; kk < CK; kk += 8) {
            int mi = wid * 16 + g;
            int ra0 = (kk + q) * RS_A, ra1 = (kk + q + 4) * RS_A;
            unsigned a0 = __float_as_uint(As_hi[ra0 + mi]);
            unsigned a1 = __float_as_uint(As_hi[ra0 + mi + 8]);
            unsigned a2 = __float_as_uint(As_hi[ra1 + mi]);
            unsigned a3 = __float_as_uint(As_hi[ra1 + mi + 8]);
            unsigned l0 = __float_as_uint(As_lo[ra0 + mi]);
            unsigned l1 = __float_as_uint(As_lo[ra0 + mi + 8]);
            unsigned l2 = __float_as_uint(As_lo[ra1 + mi]);
            unsigned l3 = __float_as_uint(As_lo[ra1 + mi + 8]);
#pragma unroll
            for (int nt = 0; nt < 6; nt++) {
                int ni = nt * 8 + g;
                int rb0 = (kk + q) * RS_B2, rb1 = (kk + q + 4) * RS_B2;
                unsigned bh0 = __float_as_uint(Bs_hi[rb0 + ni]);
                unsigned bh1 = __float_as_uint(Bs_hi[rb1 + ni]);
                unsigned bl0 = __float_as_uint(Bs_lo[rb0 + ni]);
                unsigned bl1 = __float_as_uint(Bs_lo[rb1 + ni]);
                mma_tf32(c[nt], a0, a1, a2, a3, bh0, bh1);
                mma_tf32(c[nt], l0, l1, l2, l3, bh0, bh1);
                mma_tf32(c[nt], a0, a1, a2, a3, bl0, bl1);
            }
        }
    }
    int row = row0 + wid * 16 + g;
    float wd0 = (row < NN) ? g_dinv[row] : 0.f;
    float wd1 = (row + 8 < NN) ? g_dinv[row + 8] : 0.f;
#pragma unroll
    for (int nt = 0; nt < 6; nt++) {
        int col = nt * 8 + 2 * q;
        if (row < NN)
            *(__half2*)&g_hws[row * NC_PAD + col] =
                __floats2half2_rn(c[nt][0] * wd0, c[nt][1] * wd0);
        if (row + 8 < NN)
            *(__half2*)&g_hws[(row + 8) * NC_PAD + col] =
                __floats2half2_rn(c[nt][2] * wd1, c[nt][3] * wd1);
    }
}

// ---------------- layer 2 aggregation: 8 threads per node, fp16 tree gathers ----------------
// out[d] = dinv[d] * ( hws[d] + sum_s hws[s] ) + b2
__global__ void k_agg2(const float* __restrict__ b2, float* __restrict__ out) {
    int t = blockIdx.x * blockDim.x + threadIdx.x;
    int node = t >> 3, sub = t & 7;
    if (node >= NN) return;
    bool act = sub < 6;
    const uint4* hw4 = (const uint4*)g_hws;   // 6 uint4 per row
    float acc[8] = {0.f, 0.f, 0.f, 0.f, 0.f, 0.f, 0.f, 0.f};
    if (act) acc8_add(acc, hw4[node * 6 + sub]);   // self loop (exact)
    int start = g_rowstart[node];
    int end = start + g_degi[node];
    int j = start;
    for (; j + 3 < end; j += 4) {
        int s0 = g_csr[j], s1 = g_csr[j + 1], s2 = g_csr[j + 2], s3 = g_csr[j + 3];
        if (act) {
            uint4 v0 = hw4[s0 * 6 + sub];
            uint4 v1 = hw4[s1 * 6 + sub];
            uint4 v2 = hw4[s2 * 6 + sub];
            uint4 v3 = hw4[s3 * 6 + sub];
            acc8_add4(acc, v0, v1, v2, v3);
        }
    }
    for (; j < end; j++) {
        int s0 = g_csr[j];
        if (act) acc8_add(acc, hw4[s0 * 6 + sub]);
    }
    if (act) {
        float wd = g_dinv[node];
        int cb = sub * 8;
#pragma unroll
        for (int i = 0; i < 8; i++) {
            int col = cb + i;
            if (col < NC) out[node * NC + col] = acc[i] * wd + b2[col];
        }
    }
}

extern "C" void kernel_launch(void* const* d_in, const int* in_sizes, int n_in,
                              void* d_out, int out_size) {
    const float* x  = (const float*)d_in[0];
    const int*   ei = (const int*)d_in[1];
    const float* W1 = (const float*)d_in[2];
    const float* b1 = (const float*)d_in[3];
    const float* W2 = (const float*)d_in[4];
    const float* b2 = (const float*)d_in[5];
    float* out = (float*)d_out;

    void* degi_ptr = nullptr;
    cudaGetSymbolAddress(&degi_ptr, g_degi);
    cudaMemsetAsync(degi_ptr, 0, NN_PAD * sizeof(int));

    k_deg<<<(EE + 255) / 256, 256>>>(ei);               // 0
    k_scan<<<1, 1024>>>();                              // 1
    k_fill_conv<<<(EE + 255) / 256, 256>>>(ei, x);      // 2
    k_agg1<<<(NN * 32 + 255) / 256, 256>>>();           // 3 (profiled)
    k_gemm1<<<(NN + 63) / 64, 128>>>(W1, b1);           // 4
    k_gemm2<<<(NN + 63) / 64, 128>>>(W2);               // 5
    k_agg2<<<(NN * 8 + 255) / 256, 256>>>(b2, out);     // 6
}

// round 9
// speedup vs baseline: 1.0936x; 1.0510x over previous
#include <cuda_runtime.h>
#include <cuda_fp16.h>

#define NN 100000
#define NN_PAD 102400
#define EE 1600000
#define FIN 100
#define XS_W 104          // fp16 row width (13 x 8 halves, 16B chunks)
#define HID 128
#define NC 47
#define NC_PAD 48

// GEMM tiling
#define CK 16
#define RS_A 73
#define RS_B1 136
#define RS_B2 56

__device__ int    g_degi[NN_PAD];
__device__ int    g_rowstart[NN];
__device__ int    g_eord[EE];
__device__ int    g_csr[EE];
__device__ float  g_dinv[NN];
__device__ __half g_xs[NN * XS_W];     // fp16( dinv[s] * x[s] ), padded rows
__device__ float  g_aggx[NN * FIN];
__device__ float  g_h[NN * HID];
__device__ __half g_hws[NN * NC_PAD];  // fp16( dinv[r] * (h@W2)[r] )

__device__ __forceinline__ void mma_tf32(float c[4], unsigned a0, unsigned a1,
                                         unsigned a2, unsigned a3,
                                         unsigned b0, unsigned b1) {
    asm volatile(
        "mma.sync.aligned.m16n8k8.row.col.f32.tf32.tf32.f32 "
        "{%0,%1,%2,%3}, {%4,%5,%6,%7}, {%8,%9}, {%0,%1,%2,%3};"
        : "+f"(c[0]), "+f"(c[1]), "+f"(c[2]), "+f"(c[3])
        : "r"(a0), "r"(a1), "r"(a2), "r"(a3), "r"(b0), "r"(b1));
}

__device__ __forceinline__ void split_hl(float v, float& hi, float& lo) {
    unsigned hbits = __float_as_uint(v) & 0xffffe000u;
    hi = __uint_as_float(hbits);
    lo = v - hi;
}

// exact fp32 convert-add of one uint4 of halves
__device__ __forceinline__ void acc8_add(float acc[8], uint4 v) {
    __half2* h = (__half2*)&v;
    float2 f0 = __half22float2(h[0]);
    float2 f1 = __half22float2(h[1]);
    float2 f2 = __half22float2(h[2]);
    float2 f3 = __half22float2(h[3]);
    acc[0] += f0.x; acc[1] += f0.y;
    acc[2] += f1.x; acc[3] += f1.y;
    acc[4] += f2.x; acc[5] += f2.y;
    acc[6] += f3.x; acc[7] += f3.y;
}

// fp16 tree-reduce 4 rows, one convert, fp32 accumulate
__device__ __forceinline__ void acc8_add4(float acc[8], uint4 a, uint4 b, uint4 c, uint4 d) {
    __half2* ha = (__half2*)&a;
    __half2* hb = (__half2*)&b;
    __half2* hc = (__half2*)&c;
    __half2* hd = (__half2*)&d;
#pragma unroll
    for (int k = 0; k < 4; k++) {
        __half2 s = __hadd2(__hadd2(ha[k], hb[k]), __hadd2(hc[k], hd[k]));
        float2 f = __half22float2(s);
        acc[2 * k] += f.x;
        acc[2 * k + 1] += f.y;
    }
}

// ---------------- CSR build ----------------
__global__ void k_deg(const int* __restrict__ ei) {
    int e = blockIdx.x * blockDim.x + threadIdx.x;
    if (e < EE) g_eord[e] = atomicAdd(&g_degi[ei[EE + e]], 1);
}

__global__ void k_scan() {
    __shared__ int sh_w[32];
    __shared__ int sh_tot;
    int tid = threadIdx.x;
    int lane = tid & 31, wid = tid >> 5;
    int carry = 0;
    for (int base = 0; base < NN_PAD; base += 4096) {
        int i0 = base + tid * 4;
        int4 d = ((const int4*)g_degi)[i0 >> 2];
        int s0 = d.x, s1 = s0 + d.y, s2 = s1 + d.z, s3 = s2 + d.w;
        int tsum = s3;
        int v = tsum;
        #pragma unroll
        for (int off = 1; off < 32; off <<= 1) {
            int t = __shfl_up_sync(0xffffffffu, v, off);
            if (lane >= off) v += t;
        }
        int wexcl = v - tsum;
        if (lane == 31) sh_w[wid] = v;
        __syncthreads();
        if (wid == 0) {
            int wv = sh_w[lane];
            int u = wv;
            #pragma unroll
            for (int off = 1; off < 32; off <<= 1) {
                int t = __shfl_up_sync(0xffffffffu, u, off);
                if (lane >= off) u += t;
            }
            sh_w[lane] = u - wv;
            if (lane == 31) sh_tot = u;
        }
        __syncthreads();
        int off0 = carry + sh_w[wid] + wexcl;
        if (i0 + 0 < NN) { g_rowstart[i0 + 0] = off0;      g_dinv[i0 + 0] = rsqrtf((float)d.x + 1.f); }
        if (i0 + 1 < NN) { g_rowstart[i0 + 1] = off0 + s0; g_dinv[i0 + 1] = rsqrtf((float)d.y + 1.f); }
        if (i0 + 2 < NN) { g_rowstart[i0 + 2] = off0 + s1; g_dinv[i0 + 2] = rsqrtf((float)d.z + 1.f); }
        if (i0 + 3 < NN) { g_rowstart[i0 + 3] = off0 + s2; g_dinv[i0 + 3] = rsqrtf((float)d.w + 1.f); }
        carry += sh_tot;
        __syncthreads();
    }
}

// fill CSR + build fp16 scaled feature table (needs dinv => after scan)
__global__ void k_fill_conv(const int* __restrict__ ei, const float* __restrict__ x) {
    int t = blockIdx.x * blockDim.x + threadIdx.x;
    if (t < EE)
        g_csr[g_rowstart[ei[EE + t]] + g_eord[t]] = ei[t];
    if (t < NN * 13) {
        int n = t / 13, c = t - n * 13;
        float w = g_dinv[n];
        int base = c * 8;
        float f[8];
#pragma unroll
        for (int i = 0; i < 8; i++) {
            int col = base + i;
            float v = 0.f;
            if (col < FIN) v = x[n * FIN + col] * w;
            f[i] = v;
        }
        __half2 hh[4];
        hh[0] = __floats2half2_rn(f[0], f[1]);
        hh[1] = __floats2half2_rn(f[2], f[3]);
        hh[2] = __floats2half2_rn(f[4], f[5]);
        hh[3] = __floats2half2_rn(f[6], f[7]);
        ((uint4*)g_xs)[n * 13 + c] = *(uint4*)hh;
    }
}

// ---------------- layer 1 aggregation: TWO nodes per warp (16-lane subgroups) ----------------
// aggx[d] = dinv[d] * ( xs[d] + sum_s xs[s] ),  xs already dinv-scaled
__global__ void __launch_bounds__(256) k_agg1() {
    int t = blockIdx.x * blockDim.x + threadIdx.x;
    int warp = t >> 5, lane = t & 31;
    int sub = lane >> 4;         // 0 or 1: which node of the pair
    int l = lane & 15;           // lane within subgroup
    int node = warp * 2 + sub;
    if (node >= NN) return;
    bool act = l < 13;
    const uint4* xs4 = (const uint4*)g_xs;   // 13 uint4 per row
    float acc[8] = {0.f, 0.f, 0.f, 0.f, 0.f, 0.f, 0.f, 0.f};
    if (act) acc8_add(acc, xs4[node * 13 + l]);      // self loop (exact)
    int start = g_rowstart[node];
    int end = start + g_degi[node];
    int j = start;
    for (; j + 3 < end; j += 4) {
        int s0 = g_csr[j], s1 = g_csr[j + 1], s2 = g_csr[j + 2], s3 = g_csr[j + 3];
        if (act) {
            uint4 v0 = xs4[s0 * 13 + l];
            uint4 v1 = xs4[s1 * 13 + l];
            uint4 v2 = xs4[s2 * 13 + l];
            uint4 v3 = xs4[s3 * 13 + l];
            acc8_add4(acc, v0, v1, v2, v3);
        }
    }
    for (; j < end; j++) {
        int s0 = g_csr[j];
        if (act) acc8_add(acc, xs4[s0 * 13 + l]);    // exact remainder
    }
    if (act) {
        float wd = g_dinv[node];
#pragma unroll
        for (int i = 0; i < 8; i++) acc[i] *= wd;
        int ob = node * FIN + l * 8;
        *(float4*)&g_aggx[ob] = make_float4(acc[0], acc[1], acc[2], acc[3]);
        if (l < 12)
            *(float4*)&g_aggx[ob + 4] = make_float4(acc[4], acc[5], acc[6], acc[7]);
    }
}

// ---------------- GEMM1 (3xTF32 mma): g_h = relu(g_aggx @ W1 + b1) ----------------
__global__ void __launch_bounds__(128) k_gemm1(const float* __restrict__ W1,
                                               const float* __restrict__ b1) {
    __shared__ float As_hi[CK * RS_A], As_lo[CK * RS_A];
    __shared__ float Bs_hi[CK * RS_B1], Bs_lo[CK * RS_B1];
    int tid = threadIdx.x;
    int lane = tid & 31, wid = tid >> 5;
    int g = lane >> 2, q = lane & 3;
    int warp_m = wid & 1, warp_n = wid >> 1;
    int row0 = blockIdx.x * 64;
    float c[2][8][4];
#pragma unroll
    for (int mt = 0; mt < 2; mt++)
#pragma unroll
        for (int nt = 0; nt < 8; nt++)
#pragma unroll
            for (int r = 0; r < 4; r++) c[mt][nt][r] = 0.f;

    for (int kc = 0; kc < FIN; kc += CK) {
        int kw = FIN - kc; if (kw > CK) kw = CK;
        __syncthreads();
        for (int i = tid; i < 64 * CK; i += 128) {
            int m = i >> 4, k = i & 15;
            float v = 0.f;
            int gr = row0 + m;
            if (k < kw && gr < NN) v = g_aggx[gr * FIN + kc + k];
            float hi, lo; split_hl(v, hi, lo);
            As_hi[k * RS_A + m] = hi;
            As_lo[k * RS_A + m] = lo;
        }
        for (int i = tid; i < CK * HID; i += 128) {
            int k = i >> 7, n = i & 127;
            float v = (k < kw) ? W1[(kc + k) * HID + n] : 0.f;
            float hi, lo; split_hl(v, hi, lo);
            Bs_hi[k * RS_B1 + n] = hi;
            Bs_lo[k * RS_B1 + n] = lo;
        }
        __syncthreads();
#pragma unroll
        for (int kk = 0; kk < CK; kk += 8) {
            unsigned ah[2][4], al[2][4];
#pragma unroll
            for (int mt = 0; mt < 2; mt++) {
                int mi = warp_m * 32 + mt * 16 + g;
                int r0 = (kk + q) * RS_A, r1 = (kk + q + 4) * RS_A;
                ah[mt][0] = __float_as_uint(As_hi[r0 + mi]);
                ah[mt][1] = __float_as_uint(As_hi[r0 + mi + 8]);
                ah[mt][2] = __float_as_uint(As_hi[r1 + mi]);
                ah[mt][3] = __float_as_uint(As_hi[r1 + mi + 8]);
                al[mt][0] = __float_as_uint(As_lo[r0 + mi]);
                al[mt][1] = __float_as_uint(As_lo[r0 + mi + 8]);
                al[mt][2] = __float_as_uint(As_lo[r1 + mi]);
                al[mt][3] = __float_as_uint(As_lo[r1 + mi + 8]);
            }
#pragma unroll
            for (int nt = 0; nt < 8; nt++) {
                int ni = warp_n * 64 + nt * 8 + g;
                int r0 = (kk + q) * RS_B1, r1 = (kk + q + 4) * RS_B1;
                unsigned bh0 = __float_as_uint(Bs_hi[r0 + ni]);
                unsigned bh1 = __float_as_uint(Bs_hi[r1 + ni]);
                unsigned bl0 = __float_as_uint(Bs_lo[r0 + ni]);
                unsigned bl1 = __float_as_uint(Bs_lo[r1 + ni]);
#pragma unroll
                for (int mt = 0; mt < 2; mt++) {
                    mma_tf32(c[mt][nt], ah[mt][0], ah[mt][1], ah[mt][2], ah[mt][3], bh0, bh1);
                    mma_tf32(c[mt][nt], al[mt][0], al[mt][1], al[mt][2], al[mt][3], bh0, bh1);
                    mma_tf32(c[mt][nt], ah[mt][0], ah[mt][1], ah[mt][2], ah[mt][3], bl0, bl1);
                }
            }
        }
    }
#pragma unroll
    for (int mt = 0; mt < 2; mt++) {
        int row = row0 + warp_m * 32 + mt * 16 + g;
#pragma unroll
        for (int nt = 0; nt < 8; nt++) {
            int col = warp_n * 64 + nt * 8 + 2 * q;
            float bb0 = b1[col], bb1 = b1[col + 1];
            if (row < NN) {
                float v0 = c[mt][nt][0] + bb0, v1 = c[mt][nt][1] + bb1;
                float2 o = make_float2(v0 > 0.f ? v0 : 0.f, v1 > 0.f ? v1 : 0.f);
                *(float2*)&g_h[row * HID + col] = o;
            }
            if (row + 8 < NN) {
                float v2 = c[mt][nt][2] + bb0, v3 = c[mt][nt][3] + bb1;
                float2 o = make_float2(v2 > 0.f ? v2 : 0.f, v3 > 0.f ? v3 : 0.f);
                *(float2*)&g_h[(row + 8) * HID + col] = o;
            }
        }
    }
}

// ---------------- GEMM2 (3xTF32 mma): g_hws = fp16( dinv * (g_h @ W2) ) ----------------
__global__ void __launch_bounds__(128) k_gemm2(const float* __restrict__ W2) {
    __shared__ float As_hi[CK * RS_A], As_lo[CK * RS_A];
    __shared__ float Bs_hi[CK * RS_B2], Bs_lo[CK * RS_B2];
    int tid = threadIdx.x;
    int lane = tid & 31, wid = tid >> 5;
    int g = lane >> 2, q = lane & 3;
    int row0 = blockIdx.x * 64;
    float c[6][4];
#pragma unroll
    for (int nt = 0; nt < 6; nt++)
#pragma unroll
        for (int r = 0; r < 4; r++) c[nt][r] = 0.f;

    for (int kc = 0; kc < HID; kc += CK) {
        __syncthreads();
        for (int i = tid; i < 64 * CK; i += 128) {
            int m = i >> 4, k = i & 15;
            int gr = row0 + m;
            float v = (gr < NN) ? g_h[gr * HID + kc + k] : 0.f;
            float hi, lo; split_hl(v, hi, lo);
            As_hi[k * RS_A + m] = hi;
            As_lo[k * RS_A + m] = lo;
        }
        for (int i = tid; i < CK * NC_PAD; i += 128) {
            int k = i / NC_PAD, n = i - k * NC_PAD;
            float v = (n < NC) ? W2[(kc + k) * NC + n] : 0.f;
            float hi, lo; split_hl(v, hi, lo);
            Bs_hi[k * RS_B2 + n] = hi;
            Bs_lo[k * RS_B2 + n] = lo;
        }
        __syncthreads();
#pragma unroll
        for (int kk = 0; kk < CK; kk += 8) {
            int mi = wid * 16 + g;
            int ra0 = (kk + q) * RS_A, ra1 = (kk + q + 4) * RS_A;
            unsigned a0 = __float_as_uint(As_hi[ra0 + mi]);
            unsigned a1 = __float_as_uint(As_hi[ra0 + mi + 8]);
            unsigned a2 = __float_as_uint(As_hi[ra1 + mi]);
            unsigned a3 = __float_as_uint(As_hi[ra1 + mi + 8]);
            unsigned l0 = __float_as_uint(As_lo[ra0 + mi]);
            unsigned l1 = __float_as_uint(As_lo[ra0 + mi + 8]);
            unsigned l2 = __float_as_uint(As_lo[ra1 + mi]);
            unsigned l3 = __float_as_uint(As_lo[ra1 + mi + 8]);
#pragma unroll
            for (int nt = 0; nt < 6; nt++) {
                int ni = nt * 8 + g;
                int rb0 = (kk + q) * RS_B2, rb1 = (kk + q + 4) * RS_B2;
                unsigned bh0 = __float_as_uint(Bs_hi[rb0 + ni]);
                unsigned bh1 = __float_as_uint(Bs_hi[rb1 + ni]);
                unsigned bl0 = __float_as_uint(Bs_lo[rb0 + ni]);
                unsigned bl1 = __float_as_uint(Bs_lo[rb1 + ni]);
                mma_tf32(c[nt], a0, a1, a2, a3, bh0, bh1);
                mma_tf32(c[nt], l0, l1, l2, l3, bh0, bh1);
                mma_tf32(c[nt], a0, a1, a2, a3, bl0, bl1);
            }
        }
    }
    int row = row0 + wid * 16 + g;
    float wd0 = (row < NN) ? g_dinv[row] : 0.f;
    float wd1 = (row + 8 < NN) ? g_dinv[row + 8] : 0.f;
#pragma unroll
    for (int nt = 0; nt < 6; nt++) {
        int col = nt * 8 + 2 * q;
        if (row < NN)
            *(__half2*)&g_hws[row * NC_PAD + col] =
                __floats2half2_rn(c[nt][0] * wd0, c[nt][1] * wd0);
        if (row + 8 < NN)
            *(__half2*)&g_hws[(row + 8) * NC_PAD + col] =
                __floats2half2_rn(c[nt][2] * wd1, c[nt][3] * wd1);
    }
}

// ---------------- layer 2 aggregation: 8 threads per node, fp16 tree gathers ----------------
// out[d] = dinv[d] * ( hws[d] + sum_s hws[s] ) + b2
__global__ void k_agg2(const float* __restrict__ b2, float* __restrict__ out) {
    int t = blockIdx.x * blockDim.x + threadIdx.x;
    int node = t >> 3, sub = t & 7;
    if (node >= NN) return;
    bool act = sub < 6;
    const uint4* hw4 = (const uint4*)g_hws;   // 6 uint4 per row
    float acc[8] = {0.f, 0.f, 0.f, 0.f, 0.f, 0.f, 0.f, 0.f};
    if (act) acc8_add(acc, hw4[node * 6 + sub]);   // self loop (exact)
    int start = g_rowstart[node];
    int end = start + g_degi[node];
    int j = start;
    for (; j + 3 < end; j += 4) {
        int s0 = g_csr[j], s1 = g_csr[j + 1], s2 = g_csr[j + 2], s3 = g_csr[j + 3];
        if (act) {
            uint4 v0 = hw4[s0 * 6 + sub];
            uint4 v1 = hw4[s1 * 6 + sub];
            uint4 v2 = hw4[s2 * 6 + sub];
            uint4 v3 = hw4[s3 * 6 + sub];
            acc8_add4(acc, v0, v1, v2, v3);
        }
    }
    for (; j < end; j++) {
        int s0 = g_csr[j];
        if (act) acc8_add(acc, hw4[s0 * 6 + sub]);
    }
    if (act) {
        float wd = g_dinv[node];
        int cb = sub * 8;
#pragma unroll
        for (int i = 0; i < 8; i++) {
            int col = cb + i;
            if (col < NC) out[node * NC + col] = acc[i] * wd + b2[col];
        }
    }
}

extern "C" void kernel_launch(void* const* d_in, const int* in_sizes, int n_in,
                              void* d_out, int out_size) {
    const float* x  = (const float*)d_in[0];
    const int*   ei = (const int*)d_in[1];
    const float* W1 = (const float*)d_in[2];
    const float* b1 = (const float*)d_in[3];
    const float* W2 = (const float*)d_in[4];
    const float* b2 = (const float*)d_in[5];
    float* out = (float*)d_out;

    void* degi_ptr = nullptr;
    cudaGetSymbolAddress(&degi_ptr, g_degi);
    cudaMemsetAsync(degi_ptr, 0, NN_PAD * sizeof(int));

    k_deg<<<(EE + 255) / 256, 256>>>(ei);               // 0
    k_scan<<<1, 1024>>>();                              // 1
    k_fill_conv<<<(EE + 255) / 256, 256>>>(ei, x);      // 2
    k_agg1<<<(NN * 16 + 255) / 256, 256>>>();           // 3 (profiled; 2 nodes/warp)
    k_gemm1<<<(NN + 63) / 64, 128>>>(W1, b1);           // 4
    k_gemm2<<<(NN + 63) / 64, 128>>>(W2);               // 5
    k_agg2<<<(NN * 8 + 255) / 256, 256>>>(b2, out);     // 6
}